// round 15
// baseline (speedup 1.0000x reference)
#include <cuda_runtime.h>
#include <cuda_fp16.h>

#define N_NODES 10000
#define NB 32
#define SROW 2048            // halves per node row (state part)
#define SROWQ 256            // uint4 per row
#define CAP 128              // bucket capacity per row (max row len ~55; P(>=96)~1e-18)
#define XS_ELEMS (N_NODES * SROW)
#define S_STRIDE 640000      // N*NU per batch
#define XS_Q (XS_ELEMS / 8)

__device__ __half  g_XSh[XS_ELEMS];        // pass-1 gather source (state fp16), read-only
__device__ __half  g_XS2h[XS_ELEMS];       // pass-2 gather source (r*state fp16)
__device__ __half2 g_XIh[N_NODES * NB];    // inputs-part gather source (fp16)
__device__ float2  g_YI[N_NODES * NB];     // inputs-part spmm result (pass1 writes, pass2 reads)
__device__ __half  g_Uh[NB * S_STRIDE];    // update gate
__device__ __half  g_wT1[128 * 88];        // w1^T fp16, n-major, K padded 66->80 (stride 88)
__device__ __half  g_wT2[64 * 88];         // w2^T likewise
__device__ int     g_cnt[N_NODES];         // .bss zero on load; zeroed by pass2 for next replay
__device__ int     g_len[N_NODES];         // row length snapshot (pass1 writes, pass2 reads)
__device__ int2    g_eB[N_NODES * CAP];    // packed edges: {col<<8, val bits}

// ---------- streams/events (static init; no device memory) ----------
static cudaStream_t g_s1;
static cudaEvent_t  g_evFork, g_evBuild;
namespace {
struct HxInit {
    HxInit() {
        cudaStreamCreateWithFlags(&g_s1, cudaStreamNonBlocking);
        cudaEventCreateWithFlags(&g_evFork,  cudaEventDisableTiming);
        cudaEventCreateWithFlags(&g_evBuild, cudaEventDisableTiming);
    }
};
static HxInit g_hxinit;
}

__device__ __forceinline__ float sigf(float x) { return 1.0f / (1.0f + __expf(-x)); }

__device__ __forceinline__ void mma16816(float* c, const unsigned* a, const unsigned* b) {
    asm volatile(
        "mma.sync.aligned.m16n8k16.row.col.f32.f16.f16.f32 "
        "{%0,%1,%2,%3}, {%4,%5,%6,%7}, {%8,%9}, {%0,%1,%2,%3};"
        : "+f"(c[0]), "+f"(c[1]), "+f"(c[2]), "+f"(c[3])
        : "r"(a[0]), "r"(a[1]), "r"(a[2]), "r"(a[3]), "r"(b[0]), "r"(b[1]));
}

// ---------------- bucket scatter (packed edges, no hist/scan) ----------------
__global__ void k_scatter(const int* __restrict__ rows, const int* __restrict__ cols,
                          const float* __restrict__ vals, int nnz) {
    int i = blockIdx.x * blockDim.x + threadIdx.x;
    if (i < nnz) {
        int r = rows[i];
        int p = atomicAdd(&g_cnt[r], 1);
        if (p < CAP)
            g_eB[(r << 7) + p] = make_int2(cols[i] << 8, __float_as_int(vals[i]));
    }
}

// ---------------- weight transpose/pad (once, tiny) ----------------
__global__ void k_wprep(const float* __restrict__ w1, const float* __restrict__ w2) {
    int tid = blockIdx.x * 256 + threadIdx.x;
    if (tid < 128 * 88) {
        int n = tid / 88, k = tid - n * 88;
        g_wT1[tid] = __float2half((k < 66) ? w1[k * 128 + n] : 0.0f);
    } else if (tid < 128 * 88 + 64 * 88) {
        int j = tid - 128 * 88;
        int n = j / 88, k = j - n * 88;
        g_wT2[j] = __float2half((k < 66) ? w2[k * 64 + n] : 0.0f);
    }
}

// ---------------- fused builder (XS fp16 + XI fp16) ----------------
__global__ void k_build(const float* __restrict__ inputs, const float* __restrict__ state) {
    int id = blockIdx.x * 256 + threadIdx.x;
    if (id < XS_Q) {
        int i8 = id * 8;
        int n = i8 >> 11;
        int b = (i8 >> 6) & 31;
        int u = i8 & 63;
        const float* sp = state + (size_t)b * S_STRIDE + n * 64 + u;
        float4 s0 = *(const float4*)sp;
        float4 s1 = *(const float4*)(sp + 4);
        uint4 o;
        ((__half2*)&o)[0] = __floats2half2_rn(s0.x, s0.y);
        ((__half2*)&o)[1] = __floats2half2_rn(s0.z, s0.w);
        ((__half2*)&o)[2] = __floats2half2_rn(s1.x, s1.y);
        ((__half2*)&o)[3] = __floats2half2_rn(s1.z, s1.w);
        ((uint4*)g_XSh)[id] = o;
    } else {
        int j = id - XS_Q;
        if (j < N_NODES * NB) {
            int b = j / N_NODES, n = j - b * N_NODES;
            float2 v = *(const float2*)&inputs[b * 20000 + 2 * n];
            g_XIh[n * 32 + b] = __floats2half2_rn(v.x, v.y);
        }
    }
}

// ---------------- shared gather body (packed edges, cnt <= 128) ----------------
__device__ __forceinline__ void acc8(float* a, uint4 q, float v) {
    float2 f0 = __half22float2(*(__half2*)&q.x);
    float2 f1 = __half22float2(*(__half2*)&q.y);
    float2 f2 = __half22float2(*(__half2*)&q.z);
    float2 f3 = __half22float2(*(__half2*)&q.w);
    a[0] = fmaf(v, f0.x, a[0]); a[1] = fmaf(v, f0.y, a[1]);
    a[2] = fmaf(v, f1.x, a[2]); a[3] = fmaf(v, f1.y, a[3]);
    a[4] = fmaf(v, f2.x, a[4]); a[5] = fmaf(v, f2.y, a[5]);
    a[6] = fmaf(v, f3.x, a[6]); a[7] = fmaf(v, f3.y, a[7]);
}

__device__ __forceinline__ void gather_row(const uint4* __restrict__ X, int slot,
                                           const int2* sedge, int cnt, float* a) {
    int e = 0;
    for (; e + 4 <= cnt; e += 4) {
        int2 e0 = sedge[e + 0];
        int2 e1 = sedge[e + 1];
        int2 e2 = sedge[e + 2];
        int2 e3 = sedge[e + 3];
        uint4 q0 = __ldcs(&X[e0.x + slot]);   // e.x = col*256 (uint4 row stride)
        uint4 q1 = __ldcs(&X[e1.x + slot]);
        uint4 q2 = __ldcs(&X[e2.x + slot]);
        uint4 q3 = __ldcs(&X[e3.x + slot]);
        acc8(a, q0, __int_as_float(e0.y));
        acc8(a, q1, __int_as_float(e1.y));
        acc8(a, q2, __int_as_float(e2.y));
        acc8(a, q3, __int_as_float(e3.y));
    }
    for (; e < cnt; e++) {
        int2 e0 = sedge[e];
        uint4 q = __ldcs(&X[e0.x + slot]);
        acc8(a, q, __int_as_float(e0.y));
    }
}

// Stage this block's 16x(2+64) tile (+zero pad to K=80) into A[16][88].
// y is only meaningful on owner lanes (slot%8==0).
__device__ __forceinline__ void stage_A(__half* A, int slot, const float* a, float2 y) {
    int row = (slot >> 3) & 15;
    int colb = 2 + (slot & 7) * 8;
#pragma unroll
    for (int i = 0; i < 4; i++) {
        __half2 hv = __floats2half2_rn(a[2 * i], a[2 * i + 1]);
        *(unsigned*)&A[row * 88 + colb + 2 * i] = *(unsigned*)&hv;
    }
    int r7 = slot & 7;
    if (r7 == 0) {
        __half2 hv = __floats2half2_rn(y.x, y.y);
        *(unsigned*)&A[row * 88] = *(unsigned*)&hv;
    } else if (r7 == 1) {
        unsigned* p = (unsigned*)&A[row * 88 + 66];
        p[0] = 0; p[1] = 0; p[2] = 0; p[3] = 0;      // halves 66..73
    } else if (r7 == 2) {
        unsigned* p = (unsigned*)&A[row * 88 + 74];
        p[0] = 0; p[1] = 0; p[2] = 0; p[3] = 0;      // halves 74..81 (79 is last read)
    }
}

// ---------------- pass 1: SpMM + owner-lane YI + GEMM1 + sigmoid ----------------
__global__ void __launch_bounds__(128, 10) k_spmm1f(const float* __restrict__ bias) {
    __shared__ int2   sedge[128];
    __shared__ __half A[16 * 88];
    int n = blockIdx.x >> 1;
    int h0 = blockIdx.x & 1;
    int tid = threadIdx.x;
    int slot = (h0 << 7) + tid;
    int cnt = __ldg(&g_cnt[n]);
    if (tid == 0 && h0 == 0) g_len[n] = cnt;     // snapshot for pass 2
    if (tid < cnt) sedge[tid] = g_eB[(n << 7) + tid];
    __syncthreads();

    float a[8] = {0.f, 0.f, 0.f, 0.f, 0.f, 0.f, 0.f, 0.f};
    gather_row((const uint4*)g_XSh, slot, sedge, cnt, a);

    // owner lanes: inputs-part SpMM from staged edge list (post-loop)
    float2 y = make_float2(0.f, 0.f);
    int brow = slot >> 3;
    if ((slot & 7) == 0) {
        for (int e = 0; e < cnt; e++) {
            int2 ed = sedge[e];
            float2 x = __half22float2(g_XIh[(ed.x >> 8) * 32 + brow]);
            float v = __int_as_float(ed.y);
            y.x = fmaf(v, x.x, y.x);
            y.y = fmaf(v, x.y, y.y);
        }
        g_YI[n * 32 + brow] = y;                 // for pass 2
    }
    stage_A(A, slot, a, y);
    __syncthreads();

    int lane = tid & 31, w = tid >> 5;
    int g = lane >> 2, tig = lane & 3;
    float acc[4][4] = {};
#pragma unroll
    for (int ks = 0; ks < 5; ks++) {
        int k0 = ks * 16 + 2 * tig;
        unsigned af[4];
        af[0] = *(const unsigned*)&A[g * 88 + k0];
        af[1] = *(const unsigned*)&A[(g + 8) * 88 + k0];
        af[2] = *(const unsigned*)&A[g * 88 + k0 + 8];
        af[3] = *(const unsigned*)&A[(g + 8) * 88 + k0 + 8];
#pragma unroll
        for (int nt = 0; nt < 4; nt++) {
            int nn = 32 * w + 8 * nt + g;
            unsigned bf[2];
            bf[0] = __ldg((const unsigned*)&g_wT1[nn * 88 + k0]);
            bf[1] = __ldg((const unsigned*)&g_wT1[nn * 88 + k0 + 8]);
            mma16816(acc[nt], af, bf);
        }
    }

    bool rside = (n < 5000);
#pragma unroll
    for (int nt = 0; nt < 4; nt++) {
        int j = 32 * w + 8 * nt + 2 * tig;         // output cols j, j+1
        float2 bb = *(const float2*)&bias[j];
#pragma unroll
        for (int h = 0; h < 2; h++) {
            int b = 16 * h0 + g + 8 * h;
            float v0 = sigf(acc[nt][2 * h]     + bb.x);
            float v1 = sigf(acc[nt][2 * h + 1] + bb.y);
            if (rside) {
                int t = 2 * n + (j >> 6);
                size_t off = (size_t)t * SROW + b * 64 + (j & 63);
                float2 s = __half22float2(*(const __half2*)&g_XSh[off]);
                __half2 hv = __floats2half2_rn(v0 * s.x, v1 * s.y);
                __stcs((unsigned*)&g_XS2h[off], *(unsigned*)&hv);
            } else {
                size_t off = (size_t)b * S_STRIDE + (n - 5000) * 128 + j;
                __half2 hv = __floats2half2_rn(v0, v1);
                __stcs((unsigned*)&g_Uh[off], *(unsigned*)&hv);
            }
        }
    }
}

// ---------------- pass 2: SpMM + GEMM2 + relu + GRU combine -> out ----------------
__global__ void __launch_bounds__(128, 10) k_spmm2f(const float* __restrict__ bias,
                                                    const float* __restrict__ state,
                                                    float* __restrict__ out) {
    __shared__ int2   sedge[128];
    __shared__ __half A[16 * 88];
    int n = blockIdx.x >> 1;
    int h0 = blockIdx.x & 1;
    int tid = threadIdx.x;
    int slot = (h0 << 7) + tid;
    int cnt = __ldg(&g_len[n]);
    if (tid == 0 && h0 == 0) g_cnt[n] = 0;       // clean for next replay's scatter
    if (tid < cnt) sedge[tid] = g_eB[(n << 7) + tid];
    __syncthreads();

    float a[8] = {0.f, 0.f, 0.f, 0.f, 0.f, 0.f, 0.f, 0.f};
    gather_row((const uint4*)g_XS2h, slot, sedge, cnt, a);

    float2 y = make_float2(0.f, 0.f);
    int brow = slot >> 3;
    if ((slot & 7) == 0) y = g_YI[n * 32 + brow];    // inputs-part from pass 1
    stage_A(A, slot, a, y);
    __syncthreads();

    int lane = tid & 31, w = tid >> 5;
    int g = lane >> 2, tig = lane & 3;
    float acc[2][4] = {};
#pragma unroll
    for (int ks = 0; ks < 5; ks++) {
        int k0 = ks * 16 + 2 * tig;
        unsigned af[4];
        af[0] = *(const unsigned*)&A[g * 88 + k0];
        af[1] = *(const unsigned*)&A[(g + 8) * 88 + k0];
        af[2] = *(const unsigned*)&A[g * 88 + k0 + 8];
        af[3] = *(const unsigned*)&A[(g + 8) * 88 + k0 + 8];
#pragma unroll
        for (int nt = 0; nt < 2; nt++) {
            int nn = 16 * w + 8 * nt + g;
            unsigned bf[2];
            bf[0] = __ldg((const unsigned*)&g_wT2[nn * 88 + k0]);
            bf[1] = __ldg((const unsigned*)&g_wT2[nn * 88 + k0 + 8]);
            mma16816(acc[nt], af, bf);
        }
    }

#pragma unroll
    for (int nt = 0; nt < 2; nt++) {
        int j = 16 * w + 8 * nt + 2 * tig;         // cols j, j+1 (0..63)
        float2 bb = *(const float2*)&bias[j];
#pragma unroll
        for (int h = 0; h < 2; h++) {
            int b = 16 * h0 + g + 8 * h;
            float c0 = fmaxf(acc[nt][2 * h]     + bb.x, 0.0f);
            float c1 = fmaxf(acc[nt][2 * h + 1] + bb.y, 0.0f);
            size_t off = (size_t)b * S_STRIDE + n * 64 + j;
            unsigned uu = __ldcs((const unsigned*)&g_Uh[off]);
            float2 u = __half22float2(*(__half2*)&uu);
            float2 s = *(const float2*)&state[off];
            float2 o;
            o.x = u.x * s.x + (1.0f - u.x) * c0;
            o.y = u.y * s.y + (1.0f - u.y) * c1;
            *(float2*)&out[off] = o;
        }
    }
}

// ---------------- launch ----------------
extern "C" void kernel_launch(void* const* d_in, const int* in_sizes, int n_in,
                              void* d_out, int out_size) {
    const float* inputs = (const float*)d_in[0];
    const float* state  = (const float*)d_in[1];
    const int*   m_rows = (const int*)d_in[2];
    const int*   m_cols = (const int*)d_in[3];
    const float* m_vals = (const float*)d_in[4];
    const float* w1     = (const float*)d_in[5];
    const float* b1     = (const float*)d_in[6];
    const float* w2     = (const float*)d_in[7];
    const float* b2     = (const float*)d_in[8];
    float* out = (float*)d_out;
    int nnz = in_sizes[2];

    // side: weight prep + builder, parallel with scatter
    cudaEventRecord(g_evFork, 0);
    cudaStreamWaitEvent(g_s1, g_evFork, 0);
    k_wprep<<<66, 256, 0, g_s1>>>(w1, w2);
    k_build<<<(XS_Q + N_NODES * NB + 255) / 256, 256, 0, g_s1>>>(inputs, state);
    cudaEventRecord(g_evBuild, g_s1);

    // main: bucket scatter (g_cnt is zero: .bss on first call, pass2 zeroed it last call)
    k_scatter<<<(nnz + 255) / 256, 256>>>(m_rows, m_cols, m_vals, nnz);

    // main: fused passes (need scatter [in-order] + build/wprep [event])
    cudaStreamWaitEvent(0, g_evBuild, 0);
    k_spmm1f<<<2 * N_NODES, 128>>>(b1);                 // XSh -> (XS2h, Uh, YI, len)
    k_spmm2f<<<2 * N_NODES, 128>>>(b2, state, out);     // XS2h -> out; zeroes cnt
}

// round 16
// speedup vs baseline: 1.2064x; 1.2064x over previous
#include <cuda_runtime.h>
#include <cuda_fp16.h>

#define N_NODES 10000
#define NB 32
#define SROW 2048            // halves per node row (state part)
#define SROWQ 256            // uint4 per row
#define CAP 128              // bucket capacity per row (max row len ~55; P(>=96)~1e-18)
#define XS_ELEMS (N_NODES * SROW)
#define S_STRIDE 640000      // N*NU per batch
#define XS_Q (XS_ELEMS / 8)

__device__ __half  g_XSh[XS_ELEMS];        // pass-1 gather source (state fp16), read-only
__device__ __half  g_XS2h[XS_ELEMS];       // pass-2 gather source (r*state fp16)
__device__ __half2 g_XIh[N_NODES * NB];    // inputs-part gather source (fp16)
__device__ float2  g_YI[N_NODES * NB];     // inputs-part spmm result (pass1 writes, pass2 reads)
__device__ __half  g_Uh[NB * S_STRIDE];    // update gate
__device__ __half  g_wT1[128 * 88];        // w1^T fp16, n-major, K padded 66->80 (stride 88)
__device__ __half  g_wT2[64 * 88];         // w2^T likewise
__device__ int     g_cnt[N_NODES];         // .bss zero on load; zeroed by pass2 for next replay
__device__ int     g_len[N_NODES];         // row length snapshot (pass1 writes, pass2 reads)
__device__ int2    g_eB[N_NODES * CAP];    // packed edges: {col<<8, val bits}

// ---------- streams/events (static init; no device memory) ----------
static cudaStream_t g_s1;
static cudaEvent_t  g_evFork, g_evBuild;
namespace {
struct HxInit {
    HxInit() {
        cudaStreamCreateWithFlags(&g_s1, cudaStreamNonBlocking);
        cudaEventCreateWithFlags(&g_evFork,  cudaEventDisableTiming);
        cudaEventCreateWithFlags(&g_evBuild, cudaEventDisableTiming);
    }
};
static HxInit g_hxinit;
}

__device__ __forceinline__ float sigf(float x) { return 1.0f / (1.0f + __expf(-x)); }

__device__ __forceinline__ void mma16816(float* c, const unsigned* a, const unsigned* b) {
    asm volatile(
        "mma.sync.aligned.m16n8k16.row.col.f32.f16.f16.f32 "
        "{%0,%1,%2,%3}, {%4,%5,%6,%7}, {%8,%9}, {%0,%1,%2,%3};"
        : "+f"(c[0]), "+f"(c[1]), "+f"(c[2]), "+f"(c[3])
        : "r"(a[0]), "r"(a[1]), "r"(a[2]), "r"(a[3]), "r"(b[0]), "r"(b[1]));
}

// ---------------- bucket scatter (packed edges, no hist/scan) ----------------
__global__ void k_scatter(const int* __restrict__ rows, const int* __restrict__ cols,
                          const float* __restrict__ vals, int nnz) {
    int i = blockIdx.x * blockDim.x + threadIdx.x;
    if (i < nnz) {
        int r = rows[i];
        int p = atomicAdd(&g_cnt[r], 1);
        if (p < CAP)
            g_eB[(r << 7) + p] = make_int2(cols[i] << 8, __float_as_int(vals[i]));
    }
}

// ---------------- weight transpose/pad (once, tiny) ----------------
__global__ void k_wprep(const float* __restrict__ w1, const float* __restrict__ w2) {
    int tid = blockIdx.x * 256 + threadIdx.x;
    if (tid < 128 * 88) {
        int n = tid / 88, k = tid - n * 88;
        g_wT1[tid] = __float2half((k < 66) ? w1[k * 128 + n] : 0.0f);
    } else if (tid < 128 * 88 + 64 * 88) {
        int j = tid - 128 * 88;
        int n = j / 88, k = j - n * 88;
        g_wT2[j] = __float2half((k < 66) ? w2[k * 64 + n] : 0.0f);
    }
}

// ---------------- fused builder (XS fp16 + XI fp16) ----------------
__global__ void k_build(const float* __restrict__ inputs, const float* __restrict__ state) {
    int id = blockIdx.x * 256 + threadIdx.x;
    if (id < XS_Q) {
        int i8 = id * 8;
        int n = i8 >> 11;
        int b = (i8 >> 6) & 31;
        int u = i8 & 63;
        const float* sp = state + (size_t)b * S_STRIDE + n * 64 + u;
        float4 s0 = *(const float4*)sp;
        float4 s1 = *(const float4*)(sp + 4);
        uint4 o;
        ((__half2*)&o)[0] = __floats2half2_rn(s0.x, s0.y);
        ((__half2*)&o)[1] = __floats2half2_rn(s0.z, s0.w);
        ((__half2*)&o)[2] = __floats2half2_rn(s1.x, s1.y);
        ((__half2*)&o)[3] = __floats2half2_rn(s1.z, s1.w);
        ((uint4*)g_XSh)[id] = o;
    } else {
        int j = id - XS_Q;
        if (j < N_NODES * NB) {
            int b = j / N_NODES, n = j - b * N_NODES;
            float2 v = *(const float2*)&inputs[b * 20000 + 2 * n];
            g_XIh[n * 32 + b] = __floats2half2_rn(v.x, v.y);
        }
    }
}

// ---------------- shared gather body (packed edges, cnt <= 128) ----------------
__device__ __forceinline__ void acc8(float* a, uint4 q, float v) {
    float2 f0 = __half22float2(*(__half2*)&q.x);
    float2 f1 = __half22float2(*(__half2*)&q.y);
    float2 f2 = __half22float2(*(__half2*)&q.z);
    float2 f3 = __half22float2(*(__half2*)&q.w);
    a[0] = fmaf(v, f0.x, a[0]); a[1] = fmaf(v, f0.y, a[1]);
    a[2] = fmaf(v, f1.x, a[2]); a[3] = fmaf(v, f1.y, a[3]);
    a[4] = fmaf(v, f2.x, a[4]); a[5] = fmaf(v, f2.y, a[5]);
    a[6] = fmaf(v, f3.x, a[6]); a[7] = fmaf(v, f3.y, a[7]);
}

__device__ __forceinline__ void gather_row(const uint4* __restrict__ X, int slot,
                                           const int2* sedge, int cnt, float* a) {
    int e = 0;
    for (; e + 4 <= cnt; e += 4) {
        int2 e0 = sedge[e + 0];
        int2 e1 = sedge[e + 1];
        int2 e2 = sedge[e + 2];
        int2 e3 = sedge[e + 3];
        uint4 q0 = X[e0.x + slot];     // default caching: gather rows have ~33x L2 reuse
        uint4 q1 = X[e1.x + slot];
        uint4 q2 = X[e2.x + slot];
        uint4 q3 = X[e3.x + slot];
        acc8(a, q0, __int_as_float(e0.y));
        acc8(a, q1, __int_as_float(e1.y));
        acc8(a, q2, __int_as_float(e2.y));
        acc8(a, q3, __int_as_float(e3.y));
    }
    for (; e < cnt; e++) {
        int2 e0 = sedge[e];
        uint4 q = X[e0.x + slot];
        acc8(a, q, __int_as_float(e0.y));
    }
}

// Stage this block's 16x(2+64) tile (+zero pad to K=80) into A[16][88].
// y is only meaningful on owner lanes (slot%8==0).
__device__ __forceinline__ void stage_A(__half* A, int slot, const float* a, float2 y) {
    int row = (slot >> 3) & 15;
    int colb = 2 + (slot & 7) * 8;
#pragma unroll
    for (int i = 0; i < 4; i++) {
        __half2 hv = __floats2half2_rn(a[2 * i], a[2 * i + 1]);
        *(unsigned*)&A[row * 88 + colb + 2 * i] = *(unsigned*)&hv;
    }
    int r7 = slot & 7;
    if (r7 == 0) {
        __half2 hv = __floats2half2_rn(y.x, y.y);
        *(unsigned*)&A[row * 88] = *(unsigned*)&hv;
    } else if (r7 == 1) {
        unsigned* p = (unsigned*)&A[row * 88 + 66];
        p[0] = 0; p[1] = 0; p[2] = 0; p[3] = 0;      // halves 66..73
    } else if (r7 == 2) {
        unsigned* p = (unsigned*)&A[row * 88 + 74];
        p[0] = 0; p[1] = 0; p[2] = 0; p[3] = 0;      // halves 74..81 (79 is last read)
    }
}

// ---------------- pass 1: SpMM + owner-lane YI + GEMM1 + sigmoid ----------------
__global__ void __launch_bounds__(128, 10) k_spmm1f(const float* __restrict__ bias) {
    __shared__ int2   sedge[128];
    __shared__ __half A[16 * 88];
    int n = blockIdx.x >> 1;
    int h0 = blockIdx.x & 1;
    int tid = threadIdx.x;
    int slot = (h0 << 7) + tid;
    int cnt = __ldg(&g_cnt[n]);
    if (tid == 0 && h0 == 0) g_len[n] = cnt;     // snapshot for pass 2
    if (tid < cnt) sedge[tid] = g_eB[(n << 7) + tid];
    __syncthreads();

    float a[8] = {0.f, 0.f, 0.f, 0.f, 0.f, 0.f, 0.f, 0.f};
    gather_row((const uint4*)g_XSh, slot, sedge, cnt, a);

    // owner lanes: inputs-part SpMM from staged edge list (post-loop)
    float2 y = make_float2(0.f, 0.f);
    int brow = slot >> 3;
    if ((slot & 7) == 0) {
        for (int e = 0; e < cnt; e++) {
            int2 ed = sedge[e];
            float2 x = __half22float2(g_XIh[(ed.x >> 8) * 32 + brow]);
            float v = __int_as_float(ed.y);
            y.x = fmaf(v, x.x, y.x);
            y.y = fmaf(v, x.y, y.y);
        }
        g_YI[n * 32 + brow] = y;                 // for pass 2
    }
    stage_A(A, slot, a, y);
    __syncthreads();

    int lane = tid & 31, w = tid >> 5;
    int g = lane >> 2, tig = lane & 3;
    float acc[4][4] = {};
#pragma unroll
    for (int ks = 0; ks < 5; ks++) {
        int k0 = ks * 16 + 2 * tig;
        unsigned af[4];
        af[0] = *(const unsigned*)&A[g * 88 + k0];
        af[1] = *(const unsigned*)&A[(g + 8) * 88 + k0];
        af[2] = *(const unsigned*)&A[g * 88 + k0 + 8];
        af[3] = *(const unsigned*)&A[(g + 8) * 88 + k0 + 8];
#pragma unroll
        for (int nt = 0; nt < 4; nt++) {
            int nn = 32 * w + 8 * nt + g;
            unsigned bf[2];
            bf[0] = __ldg((const unsigned*)&g_wT1[nn * 88 + k0]);
            bf[1] = __ldg((const unsigned*)&g_wT1[nn * 88 + k0 + 8]);
            mma16816(acc[nt], af, bf);
        }
    }

    bool rside = (n < 5000);
#pragma unroll
    for (int nt = 0; nt < 4; nt++) {
        int j = 32 * w + 8 * nt + 2 * tig;         // output cols j, j+1
        float2 bb = *(const float2*)&bias[j];
#pragma unroll
        for (int h = 0; h < 2; h++) {
            int b = 16 * h0 + g + 8 * h;
            float v0 = sigf(acc[nt][2 * h]     + bb.x);
            float v1 = sigf(acc[nt][2 * h + 1] + bb.y);
            if (rside) {
                int t = 2 * n + (j >> 6);
                size_t off = (size_t)t * SROW + b * 64 + (j & 63);
                float2 s = __half22float2(*(const __half2*)&g_XSh[off]);
                __half2 hv = __floats2half2_rn(v0 * s.x, v1 * s.y);
                *(unsigned*)&g_XS2h[off] = *(unsigned*)&hv;   // default store: pass 2 wants it L2-resident
            } else {
                size_t off = (size_t)b * S_STRIDE + (n - 5000) * 128 + j;
                __half2 hv = __floats2half2_rn(v0, v1);
                __stcs((unsigned*)&g_Uh[off], *(unsigned*)&hv);
            }
        }
    }
}

// ---------------- pass 2: SpMM + GEMM2 + relu + GRU combine -> out ----------------
__global__ void __launch_bounds__(128, 10) k_spmm2f(const float* __restrict__ bias,
                                                    const float* __restrict__ state,
                                                    float* __restrict__ out) {
    __shared__ int2   sedge[128];
    __shared__ __half A[16 * 88];
    int n = blockIdx.x >> 1;
    int h0 = blockIdx.x & 1;
    int tid = threadIdx.x;
    int slot = (h0 << 7) + tid;
    int cnt = __ldg(&g_len[n]);
    if (tid == 0 && h0 == 0) g_cnt[n] = 0;       // clean for next replay's scatter
    if (tid < cnt) sedge[tid] = g_eB[(n << 7) + tid];
    __syncthreads();

    float a[8] = {0.f, 0.f, 0.f, 0.f, 0.f, 0.f, 0.f, 0.f};
    gather_row((const uint4*)g_XS2h, slot, sedge, cnt, a);

    float2 y = make_float2(0.f, 0.f);
    int brow = slot >> 3;
    if ((slot & 7) == 0) y = g_YI[n * 32 + brow];    // inputs-part from pass 1
    stage_A(A, slot, a, y);
    __syncthreads();

    int lane = tid & 31, w = tid >> 5;
    int g = lane >> 2, tig = lane & 3;
    float acc[2][4] = {};
#pragma unroll
    for (int ks = 0; ks < 5; ks++) {
        int k0 = ks * 16 + 2 * tig;
        unsigned af[4];
        af[0] = *(const unsigned*)&A[g * 88 + k0];
        af[1] = *(const unsigned*)&A[(g + 8) * 88 + k0];
        af[2] = *(const unsigned*)&A[g * 88 + k0 + 8];
        af[3] = *(const unsigned*)&A[(g + 8) * 88 + k0 + 8];
#pragma unroll
        for (int nt = 0; nt < 2; nt++) {
            int nn = 16 * w + 8 * nt + g;
            unsigned bf[2];
            bf[0] = __ldg((const unsigned*)&g_wT2[nn * 88 + k0]);
            bf[1] = __ldg((const unsigned*)&g_wT2[nn * 88 + k0 + 8]);
            mma16816(acc[nt], af, bf);
        }
    }

#pragma unroll
    for (int nt = 0; nt < 2; nt++) {
        int j = 16 * w + 8 * nt + 2 * tig;         // cols j, j+1 (0..63)
        float2 bb = *(const float2*)&bias[j];
#pragma unroll
        for (int h = 0; h < 2; h++) {
            int b = 16 * h0 + g + 8 * h;
            float c0 = fmaxf(acc[nt][2 * h]     + bb.x, 0.0f);
            float c1 = fmaxf(acc[nt][2 * h + 1] + bb.y, 0.0f);
            size_t off = (size_t)b * S_STRIDE + n * 64 + j;
            unsigned uu = __ldcs((const unsigned*)&g_Uh[off]);
            float2 u = __half22float2(*(__half2*)&uu);
            float2 s = *(const float2*)&state[off];
            float2 o;
            o.x = u.x * s.x + (1.0f - u.x) * c0;
            o.y = u.y * s.y + (1.0f - u.y) * c1;
            *(float2*)&out[off] = o;
        }
    }
}

// ---------------- launch ----------------
extern "C" void kernel_launch(void* const* d_in, const int* in_sizes, int n_in,
                              void* d_out, int out_size) {
    const float* inputs = (const float*)d_in[0];
    const float* state  = (const float*)d_in[1];
    const int*   m_rows = (const int*)d_in[2];
    const int*   m_cols = (const int*)d_in[3];
    const float* m_vals = (const float*)d_in[4];
    const float* w1     = (const float*)d_in[5];
    const float* b1     = (const float*)d_in[6];
    const float* w2     = (const float*)d_in[7];
    const float* b2     = (const float*)d_in[8];
    float* out = (float*)d_out;
    int nnz = in_sizes[2];

    // side: weight prep + builder, parallel with scatter
    cudaEventRecord(g_evFork, 0);
    cudaStreamWaitEvent(g_s1, g_evFork, 0);
    k_wprep<<<66, 256, 0, g_s1>>>(w1, w2);
    k_build<<<(XS_Q + N_NODES * NB + 255) / 256, 256, 0, g_s1>>>(inputs, state);
    cudaEventRecord(g_evBuild, g_s1);

    // main: bucket scatter (g_cnt is zero: .bss on first call, pass2 zeroed it last call)
    k_scatter<<<(nnz + 255) / 256, 256>>>(m_rows, m_cols, m_vals, nnz);

    // main: fused passes (need scatter [in-order] + build/wprep [event])
    cudaStreamWaitEvent(0, g_evBuild, 0);
    k_spmm1f<<<2 * N_NODES, 128>>>(b1);                 // XSh -> (XS2h, Uh, YI, len)
    k_spmm2f<<<2 * N_NODES, 128>>>(b2, state, out);     // XS2h -> out; zeroes cnt
}